// round 1
// baseline (speedup 1.0000x reference)
#include <cuda_runtime.h>

// Fused: conv3x3(w1) -> conv3x3(w2) -> maxpool2x2 -> conv3x3(w3) -> conv3x3(w4) -> conv3x3(w5)
// N=4, C=1, 4096x4096 -> 2048x2048, fp32, zero (SAME) padding on every conv.
//
// One CTA computes a 64x64 pooled-output tile. Input tile needed: 144x144
// (halo 8 each side in input domain). All intermediates staged in shared
// memory with ping-pong buffer reuse. Out-of-image intermediate values are
// zeroed per stage to match the reference's per-stage zero padding.

#define NT    512
#define H_IN  4096
#define W_IN  4096
#define H_PO  2048
#define W_PO  2048
#define TILE  64
#define IN_T  144     // input tile side (2*TILE + 16)
#define C1W   142     // conv1 out tile side
#define C2W   140     // conv2 out tile side
#define POW_  70      // pool out tile side
#define C3W   68      // conv3 out tile side
#define C4W   66      // conv4 out tile side

#define BUF_A_FLOATS (IN_T * IN_T)   // 20736 (holds: input, conv2 out, conv3 out)
#define BUF_B_FLOATS (C1W * C1W)     // 20164 (holds: conv1 out, pool out, conv4 out)
#define SMEM_BYTES   ((BUF_A_FLOATS + BUF_B_FLOATS) * 4)   // 163600 B

extern __shared__ float smem_raw[];

// One 3x3 conv stage. Each thread computes a vertical strip of 8 outputs in
// one column (lane-adjacent threads -> adjacent columns -> conflict-free LDS,
// coalesced STS/STG). 30 shared loads / 72 FMA per 8 outputs.
// Values whose global coordinate falls outside [0,gH)x[0,gW) are written as 0
// (matches reference zero padding of the stage input for the NEXT stage).
__device__ __forceinline__ void conv3x3_stage(
    const float* __restrict__ src, const int srcW,
    float* __restrict__ dst, const int dstW, const int dstStride, const int dstH,
    const float* __restrict__ wp,
    const int grow0, const int gcol0, const int gH, const int gW)
{
    float wr[9];
#pragma unroll
    for (int q = 0; q < 9; q++) wr[q] = __ldg(wp + q);

    const int RB    = (dstH + 7) >> 3;
    const int total = RB * dstW;
    for (int i = threadIdx.x; i < total; i += NT) {
        const int c  = i % dstW;           // compile-time dstW at every call site
        const int rb = i / dstW;
        int r0 = rb << 3;
        if (r0 > dstH - 8) r0 = dstH - 8;  // overlap-clamp; duplicate writes identical

        float acc[8];
#pragma unroll
        for (int j = 0; j < 8; j++) acc[j] = 0.f;

        const float* p = src + r0 * srcW + c;
#pragma unroll
        for (int k = 0; k < 10; k++) {
            const float s0 = p[0];
            const float s1 = p[1];
            const float s2 = p[2];
            p += srcW;
#pragma unroll
            for (int j = 0; j < 8; j++) {
                const int m = k - j;       // weight row; compile-time after unroll
                if (0 <= m && m < 3) {
                    acc[j] += wr[3 * m + 0] * s0;
                    acc[j] += wr[3 * m + 1] * s1;
                    acc[j] += wr[3 * m + 2] * s2;
                }
            }
        }

        const int  gc    = gcol0 + c;
        const bool colok = (gc >= 0) & (gc < gW);
        float* d = dst + r0 * dstStride + c;
#pragma unroll
        for (int j = 0; j < 8; j++) {
            const int  gr = grow0 + r0 + j;
            const bool ok = colok & (gr >= 0) & (gr < gH);
            d[j * dstStride] = ok ? acc[j] : 0.f;
        }
    }
}

__device__ __forceinline__ void pool2x2_stage(
    const float* __restrict__ src, const int srcW,
    float* __restrict__ dst, const int dstW, const int dstH)
{
    const int RB    = (dstH + 7) >> 3;
    const int total = RB * dstW;
    for (int i = threadIdx.x; i < total; i += NT) {
        const int c  = i % dstW;
        const int rb = i / dstW;
        int r0 = rb << 3;
        if (r0 > dstH - 8) r0 = dstH - 8;

        const float* p = src + (2 * r0) * srcW + 2 * c;
#pragma unroll
        for (int j = 0; j < 8; j++) {
            const float a = p[0];
            const float b = p[1];
            const float e = p[srcW];
            const float f = p[srcW + 1];
            p += 2 * srcW;
            // Out-of-image windows read all-zero conv2 entries -> max = 0,
            // which equals the zero padding conv3 expects. No explicit check.
            dst[(r0 + j) * dstW + c] = fmaxf(fmaxf(a, b), fmaxf(e, f));
        }
    }
}

__global__ __launch_bounds__(NT, 1)
void fused_net_kernel(const float* __restrict__ x,
                      const float* __restrict__ w1, const float* __restrict__ w2,
                      const float* __restrict__ w3, const float* __restrict__ w4,
                      const float* __restrict__ w5,
                      float* __restrict__ out)
{
    float* bufA = smem_raw;                  // 20736 floats
    float* bufB = smem_raw + BUF_A_FLOATS;   // 20164 floats

    const int bx = blockIdx.x, by = blockIdx.y, bz = blockIdx.z;
    const int ix0 = bx * (2 * TILE) - 8;     // input-domain tile origin
    const int iy0 = by * (2 * TILE) - 8;
    const float* img = x + (size_t)bz * ((size_t)H_IN * W_IN);

    // ---- Load 144x144 input tile (zero-padded) as float4 where possible ----
    {
        const int NV = IN_T * (IN_T / 4);    // 5184 float4s
        for (int i = threadIdx.x; i < NV; i += NT) {
            const int r  = i / (IN_T / 4);
            const int c4 = (i - r * (IN_T / 4)) * 4;
            const int gy = iy0 + r;
            const int gx = ix0 + c4;         // gx % 4 == 0 -> 16B aligned
            float4 v;
            if (gy >= 0 && gy < H_IN && gx >= 0 && gx + 3 < W_IN) {
                v = *reinterpret_cast<const float4*>(img + (size_t)gy * W_IN + gx);
            } else {
                v.x = v.y = v.z = v.w = 0.f;
                if (gy >= 0 && gy < H_IN) {
                    const float* row = img + (size_t)gy * W_IN;
                    if (gx + 0 >= 0 && gx + 0 < W_IN) v.x = row[gx + 0];
                    if (gx + 1 >= 0 && gx + 1 < W_IN) v.y = row[gx + 1];
                    if (gx + 2 >= 0 && gx + 2 < W_IN) v.z = row[gx + 2];
                    if (gx + 3 >= 0 && gx + 3 < W_IN) v.w = row[gx + 3];
                }
            }
            *reinterpret_cast<float4*>(bufA + r * IN_T + c4) = v;
        }
    }
    __syncthreads();

    // conv1: bufA(144) -> bufB(142), global center of dst[0][0] = (iy0+1, ix0+1)
    conv3x3_stage(bufA, IN_T, bufB, C1W, C1W, C1W, w1, iy0 + 1, ix0 + 1, H_IN, W_IN);
    __syncthreads();

    // conv2: bufB(142) -> bufA(140), center (iy0+2, ix0+2)
    conv3x3_stage(bufB, C1W, bufA, C2W, C2W, C2W, w2, iy0 + 2, ix0 + 2, H_IN, W_IN);
    __syncthreads();

    // pool: bufA(140) -> bufB(70); pooled origin = (64*by-3, 64*bx-3)
    pool2x2_stage(bufA, C2W, bufB, POW_, POW_);
    __syncthreads();

    // conv3: bufB(70) -> bufA(68), pooled-domain center (64*by-2, 64*bx-2)
    conv3x3_stage(bufB, POW_, bufA, C3W, C3W, C3W, w3,
                  by * TILE - 2, bx * TILE - 2, H_PO, W_PO);
    __syncthreads();

    // conv4: bufA(68) -> bufB(66), center (64*by-1, 64*bx-1)
    conv3x3_stage(bufA, C3W, bufB, C4W, C4W, C4W, w4,
                  by * TILE - 1, bx * TILE - 1, H_PO, W_PO);
    __syncthreads();

    // conv5: bufB(66) -> gmem 64x64 (always fully in-domain)
    float* optr = out + ((size_t)bz * H_PO + (size_t)by * TILE) * W_PO + bx * TILE;
    conv3x3_stage(bufB, C4W, optr, TILE, W_PO, TILE, w5,
                  0, 0, 1 << 30, 1 << 30);
}

extern "C" void kernel_launch(void* const* d_in, const int* in_sizes, int n_in,
                              void* d_out, int out_size)
{
    const float* x  = (const float*)d_in[0];
    const float* w1 = (const float*)d_in[1];
    const float* w2 = (const float*)d_in[2];
    const float* w3 = (const float*)d_in[3];
    const float* w4 = (const float*)d_in[4];
    const float* w5 = (const float*)d_in[5];
    float* out = (float*)d_out;

    cudaFuncSetAttribute(fused_net_kernel,
                         cudaFuncAttributeMaxDynamicSharedMemorySize, SMEM_BYTES);
    dim3 grid(W_PO / TILE, H_PO / TILE, 4);   // 32 x 32 x 4 = 4096 CTAs
    fused_net_kernel<<<grid, NT, SMEM_BYTES>>>(x, w1, w2, w3, w4, w5, out);
}

// round 2
// speedup vs baseline: 1.3408x; 1.3408x over previous
#include <cuda_runtime.h>

// Fused: conv3x3(w1) -> conv3x3(w2) -> maxpool2x2 -> conv3x3(w3) -> conv3x3(w4) -> conv3x3(w5)
// N=4, C=1, 4096x4096 -> 2048x2048, fp32, zero (SAME) padding on every conv.
//
// One CTA (1024 threads) computes a 64x64 pooled-output tile from a 144x144
// input tile (halo 8). All intermediates in shared memory (ping-pong).
// Interior CTAs (900/1024) take a mask-free specialized path.

#define NT    1024
#define H_IN  4096
#define W_IN  4096
#define H_PO  2048
#define W_PO  2048
#define TILE  64
#define IN_T  144     // input tile side
#define C1W   142
#define C2W   140
#define POW_  70
#define C3W   68
#define C4W   66

#define BUF_A_FLOATS (IN_T * IN_T)   // 20736
#define BUF_B_FLOATS (C1W * C1W)     // 20164
#define SMEM_BYTES   ((BUF_A_FLOATS + BUF_B_FLOATS) * 4)   // 163600 B

extern __shared__ float smem_raw[];

// 3x3 conv stage, vertical 8-row strip per thread per iteration.
// All shape params compile-time; incremental (rb,c) indexing (no div/mod in loop).
// MASK: zero outputs whose global coordinate is outside the image (edge tiles only).
template<int srcW, int dstW, int dstStride, int dstH, bool MASK>
__device__ __forceinline__ void conv_stage(
    const float* __restrict__ src, float* __restrict__ dst,
    const float* __restrict__ wp,
    const int grow0, const int gcol0, const int gH, const int gW)
{
    float wr[9];
#pragma unroll
    for (int q = 0; q < 9; q++) wr[q] = __ldg(wp + q);

    constexpr int RB      = (dstH + 7) / 8;
    constexpr int STEP_RB = NT / dstW;
    constexpr int STEP_C  = NT % dstW;

    int rb = (int)threadIdx.x / dstW;            // one const-division, hoisted
    int c  = (int)threadIdx.x - rb * dstW;

    while (rb < RB) {
        int r0 = rb * 8;
        if (r0 > dstH - 8) r0 = dstH - 8;        // overlap-clamp (identical rewrites)

        float acc[8];
#pragma unroll
        for (int j = 0; j < 8; j++) acc[j] = 0.f;

        const float* p = src + r0 * srcW + c;
#pragma unroll
        for (int k = 0; k < 10; k++) {
            const float s0 = p[0];
            const float s1 = p[1];
            const float s2 = p[2];
            p += srcW;
#pragma unroll
            for (int j = 0; j < 8; j++) {
                const int m = k - j;             // weight row, compile-time
                if (0 <= m && m < 3) {
                    acc[j] += wr[3 * m + 0] * s0;
                    acc[j] += wr[3 * m + 1] * s1;
                    acc[j] += wr[3 * m + 2] * s2;
                }
            }
        }

        float* d = dst + r0 * dstStride + c;
        if (MASK) {
            const int  gc    = gcol0 + c;
            const bool colok = (gc >= 0) & (gc < gW);
#pragma unroll
            for (int j = 0; j < 8; j++) {
                const int  gr = grow0 + r0 + j;
                const bool ok = colok & (gr >= 0) & (gr < gH);
                d[j * dstStride] = ok ? acc[j] : 0.f;
            }
        } else {
#pragma unroll
            for (int j = 0; j < 8; j++) d[j * dstStride] = acc[j];
        }

        c  += STEP_C;
        rb += STEP_RB;
        if (STEP_C > 0 && c >= dstW) { c -= dstW; rb++; }
    }
}

template<int srcW, int dstW, int dstH>
__device__ __forceinline__ void pool_stage(
    const float* __restrict__ src, float* __restrict__ dst)
{
    constexpr int RB      = (dstH + 7) / 8;
    constexpr int STEP_RB = NT / dstW;
    constexpr int STEP_C  = NT % dstW;

    int rb = (int)threadIdx.x / dstW;
    int c  = (int)threadIdx.x - rb * dstW;

    while (rb < RB) {
        int r0 = rb * 8;
        if (r0 > dstH - 8) r0 = dstH - 8;

        const float* p = src + (2 * r0) * srcW + 2 * c;
#pragma unroll
        for (int j = 0; j < 8; j++) {
            const float a = p[0];
            const float b = p[1];
            const float e = p[srcW];
            const float f = p[srcW + 1];
            p += 2 * srcW;
            // OOB windows see zeroed conv2 entries -> max 0 == required padding.
            dst[(r0 + j) * dstW + c] = fmaxf(fmaxf(a, b), fmaxf(e, f));
        }

        c  += STEP_C;
        rb += STEP_RB;
        if (STEP_C > 0 && c >= dstW) { c -= dstW; rb++; }
    }
}

template<bool MASK>
__device__ __forceinline__ void run_tile(
    const float* __restrict__ x,
    const float* __restrict__ w1, const float* __restrict__ w2,
    const float* __restrict__ w3, const float* __restrict__ w4,
    const float* __restrict__ w5,
    float* __restrict__ out)
{
    float* bufA = smem_raw;
    float* bufB = smem_raw + BUF_A_FLOATS;

    const int bx = blockIdx.x, by = blockIdx.y, bz = blockIdx.z;
    const int ix0 = bx * (2 * TILE) - 8;
    const int iy0 = by * (2 * TILE) - 8;
    const float* img = x + (size_t)bz * ((size_t)H_IN * W_IN);

    // ---- Load 144x144 input tile as float4 ----
    {
        constexpr int NV = IN_T * (IN_T / 4);    // 5184
        for (int i = threadIdx.x; i < NV; i += NT) {
            const int r  = i / (IN_T / 4);
            const int c4 = (i - r * (IN_T / 4)) * 4;
            float4 v;
            if (!MASK) {
                v = *reinterpret_cast<const float4*>(
                        img + (size_t)(iy0 + r) * W_IN + (ix0 + c4));
            } else {
                const int gy = iy0 + r;
                const int gx = ix0 + c4;
                if (gy >= 0 && gy < H_IN && gx >= 0 && gx + 3 < W_IN) {
                    v = *reinterpret_cast<const float4*>(img + (size_t)gy * W_IN + gx);
                } else {
                    v.x = v.y = v.z = v.w = 0.f;
                    if (gy >= 0 && gy < H_IN) {
                        const float* row = img + (size_t)gy * W_IN;
                        if (gx + 0 >= 0 && gx + 0 < W_IN) v.x = row[gx + 0];
                        if (gx + 1 >= 0 && gx + 1 < W_IN) v.y = row[gx + 1];
                        if (gx + 2 >= 0 && gx + 2 < W_IN) v.z = row[gx + 2];
                        if (gx + 3 >= 0 && gx + 3 < W_IN) v.w = row[gx + 3];
                    }
                }
            }
            *reinterpret_cast<float4*>(bufA + r * IN_T + c4) = v;
        }
    }
    __syncthreads();

    conv_stage<IN_T, C1W, C1W, C1W, MASK>(bufA, bufB, w1, iy0 + 1, ix0 + 1, H_IN, W_IN);
    __syncthreads();

    conv_stage<C1W, C2W, C2W, C2W, MASK>(bufB, bufA, w2, iy0 + 2, ix0 + 2, H_IN, W_IN);
    __syncthreads();

    pool_stage<C2W, POW_, POW_>(bufA, bufB);
    __syncthreads();

    conv_stage<POW_, C3W, C3W, C3W, MASK>(bufB, bufA, w3,
                                          by * TILE - 2, bx * TILE - 2, H_PO, W_PO);
    __syncthreads();

    conv_stage<C3W, C4W, C4W, C4W, MASK>(bufA, bufB, w4,
                                         by * TILE - 1, bx * TILE - 1, H_PO, W_PO);
    __syncthreads();

    // conv5 output tile is always fully inside the image -> never masked.
    float* optr = out + ((size_t)bz * H_PO + (size_t)by * TILE) * W_PO + bx * TILE;
    conv_stage<C4W, TILE, W_PO, TILE, false>(bufB, optr, w5, 0, 0, H_PO, W_PO);
}

__global__ __launch_bounds__(NT, 1)
void fused_net_kernel(const float* __restrict__ x,
                      const float* __restrict__ w1, const float* __restrict__ w2,
                      const float* __restrict__ w3, const float* __restrict__ w4,
                      const float* __restrict__ w5,
                      float* __restrict__ out)
{
    const int bx = blockIdx.x, by = blockIdx.y;
    const bool interior = (bx > 0) & (bx < (W_PO / TILE) - 1) &
                          (by > 0) & (by < (H_PO / TILE) - 1);
    if (interior) run_tile<false>(x, w1, w2, w3, w4, w5, out);
    else          run_tile<true >(x, w1, w2, w3, w4, w5, out);
}

extern "C" void kernel_launch(void* const* d_in, const int* in_sizes, int n_in,
                              void* d_out, int out_size)
{
    const float* x  = (const float*)d_in[0];
    const float* w1 = (const float*)d_in[1];
    const float* w2 = (const float*)d_in[2];
    const float* w3 = (const float*)d_in[3];
    const float* w4 = (const float*)d_in[4];
    const float* w5 = (const float*)d_in[5];
    float* out = (float*)d_out;

    cudaFuncSetAttribute(fused_net_kernel,
                         cudaFuncAttributeMaxDynamicSharedMemorySize, SMEM_BYTES);
    dim3 grid(W_PO / TILE, H_PO / TILE, 4);   // 32 x 32 x 4
    fused_net_kernel<<<grid, NT, SMEM_BYTES>>>(x, w1, w2, w3, w4, w5, out);
}

// round 3
// speedup vs baseline: 1.4904x; 1.1116x over previous
#include <cuda_runtime.h>

// Fused: conv3x3(w1) -> conv3x3(w2) -> maxpool2x2 -> conv3x3(w3) -> conv3x3(w4) -> conv3x3(w5)
// N=4, C=1, 4096x4096 -> 2048x2048, fp32, zero (SAME) padding each conv.
//
// One CTA (1024 thr) = one 64x64 pooled-output tile from a 144x144 input tile.
// All intermediates in smem (ping-pong, strides padded to x4 for LDS.128/STS.128).
// Each stage: 4-wide x T-tall register microtile per thread, single pass
// (<=1024 items). Benign overreads land in 16-float guard zones. Interior CTAs
// (900/1024) take a fully mask-free path.

#define NT    1024
#define H_IN  4096
#define W_IN  4096
#define H_PO  2048
#define W_PO  2048
#define TILE  64
#define IN_T  144

#define BUF_A_FLOATS (144 * 144)          // 20736: input / conv2(140x140 s140) / conv3(68x68 s68)
#define BUF_B_FLOATS (142 * 144)          // 20448: conv1(142 rows s144) / pool(70x72) / conv4(66 s68)
#define GUARD 16
#define SMEM_FLOATS (BUF_A_FLOATS + GUARD + BUF_B_FLOATS + GUARD)
#define SMEM_BYTES  (SMEM_FLOATS * 4)     // 164,864 B

extern __shared__ float smem_raw[];

// 3x3 conv stage: each of the first NITEMS threads computes a 4-wide x T-tall
// output microtile. Per source row: 2x LDS.128 (8 floats, 6 used). Per output
// row: 1x STS.128 (or STG.128 for the final stage). Group count NG covers the
// width with 4-col groups; groups may write into stride padding (never read).
// MASK: zero cells whose global coordinate is outside the image.
template<int SRCW, int DSTSTRIDE, int DSTH, int T, int NG, bool MASK>
__device__ __forceinline__ void conv_stage(
    const float* __restrict__ src, float* __restrict__ dst,
    const float* __restrict__ wp,
    const int grow0, const int gcol0, const int gH, const int gW)
{
    constexpr int RB     = (DSTH + T - 1) / T;
    constexpr int NITEMS = NG * RB;
    static_assert(NITEMS <= NT, "stage must be single-pass");

    const int tid = threadIdx.x;
    if (tid >= NITEMS) return;

    float wr[9];
#pragma unroll
    for (int q = 0; q < 9; q++) wr[q] = __ldg(wp + q);

    const int g  = tid % NG;            // const-div -> mul
    const int rb = tid / NG;
    const int c0 = g * 4;
    int r0 = rb * T;
    if (r0 > DSTH - T) r0 = DSTH - T;   // overlap clamp; duplicates write identical values

    float acc[T][4];
#pragma unroll
    for (int j = 0; j < T; j++)
#pragma unroll
        for (int q = 0; q < 4; q++) acc[j][q] = 0.f;

    const float* p = src + r0 * SRCW + c0;
#pragma unroll
    for (int k = 0; k < T + 2; k++) {
        const float4 A = *reinterpret_cast<const float4*>(p);
        const float4 B = *reinterpret_cast<const float4*>(p + 4);
        p += SRCW;
        const float s[8] = {A.x, A.y, A.z, A.w, B.x, B.y, B.z, B.w};
#pragma unroll
        for (int j = 0; j < T; j++) {
            const int m = k - j;        // weight row; compile-time after unroll
            if (0 <= m && m < 3) {
#pragma unroll
                for (int q = 0; q < 4; q++) {
                    acc[j][q] = fmaf(wr[3 * m + 0], s[q + 0],
                                fmaf(wr[3 * m + 1], s[q + 1],
                                fmaf(wr[3 * m + 2], s[q + 2], acc[j][q])));
                }
            }
        }
    }

    float* d = dst + r0 * DSTSTRIDE + c0;
    if (MASK) {
        bool cok[4];
#pragma unroll
        for (int q = 0; q < 4; q++) {
            const int gc = gcol0 + c0 + q;
            cok[q] = (gc >= 0) & (gc < gW);
        }
#pragma unroll
        for (int j = 0; j < T; j++) {
            const int  gr  = grow0 + r0 + j;
            const bool rok = (gr >= 0) & (gr < gH);
            float4 v;
            v.x = (rok & cok[0]) ? acc[j][0] : 0.f;
            v.y = (rok & cok[1]) ? acc[j][1] : 0.f;
            v.z = (rok & cok[2]) ? acc[j][2] : 0.f;
            v.w = (rok & cok[3]) ? acc[j][3] : 0.f;
            *reinterpret_cast<float4*>(d + j * DSTSTRIDE) = v;
        }
    } else {
#pragma unroll
        for (int j = 0; j < T; j++) {
            const float4 v = {acc[j][0], acc[j][1], acc[j][2], acc[j][3]};
            *reinterpret_cast<float4*>(d + j * DSTSTRIDE) = v;
        }
    }
}

// 2x2 max pool, 4-wide x 2-tall per item. OOB windows see zeroed conv2 cells
// -> max 0 == the zero padding conv3 expects (padding cols contain garbage but
// are never read).
template<int SRCW, int DSTSTRIDE, int DSTH, int NG>
__device__ __forceinline__ void pool_stage(
    const float* __restrict__ src, float* __restrict__ dst)
{
    constexpr int RB     = DSTH / 2;
    constexpr int NITEMS = NG * RB;
    static_assert(NITEMS <= NT, "pool must be single-pass");

    const int tid = threadIdx.x;
    if (tid >= NITEMS) return;
    const int g  = tid % NG;
    const int rb = tid / NG;
    const int c0 = g * 4;
    const int r0 = rb * 2;

    const float* p = src + (2 * r0) * SRCW + 2 * c0;
#pragma unroll
    for (int j = 0; j < 2; j++) {
        const float4 A = *reinterpret_cast<const float4*>(p);
        const float4 B = *reinterpret_cast<const float4*>(p + 4);
        const float4 C = *reinterpret_cast<const float4*>(p + SRCW);
        const float4 D = *reinterpret_cast<const float4*>(p + SRCW + 4);
        p += 2 * SRCW;
        float4 v;
        v.x = fmaxf(fmaxf(A.x, A.y), fmaxf(C.x, C.y));
        v.y = fmaxf(fmaxf(A.z, A.w), fmaxf(C.z, C.w));
        v.z = fmaxf(fmaxf(B.x, B.y), fmaxf(D.x, D.y));
        v.w = fmaxf(fmaxf(B.z, B.w), fmaxf(D.z, D.w));
        *reinterpret_cast<float4*>(dst + (r0 + j) * DSTSTRIDE + c0) = v;
    }
}

template<bool MASK>
__device__ __forceinline__ void run_tile(
    const float* __restrict__ x,
    const float* __restrict__ w1, const float* __restrict__ w2,
    const float* __restrict__ w3, const float* __restrict__ w4,
    const float* __restrict__ w5,
    float* __restrict__ out)
{
    float* bufA = smem_raw;
    float* bufB = smem_raw + BUF_A_FLOATS + GUARD;

    const int bx = blockIdx.x, by = blockIdx.y, bz = blockIdx.z;
    const int ix0 = bx * (2 * TILE) - 8;
    const int iy0 = by * (2 * TILE) - 8;
    const float* img = x + (size_t)bz * ((size_t)H_IN * W_IN);

    // ---- Load 144x144 input tile (stride 144) as float4 ----
    {
        constexpr int NV = IN_T * (IN_T / 4);    // 5184
        for (int i = threadIdx.x; i < NV; i += NT) {
            const int r  = i / (IN_T / 4);
            const int c4 = (i - r * (IN_T / 4)) * 4;
            float4 v;
            if (!MASK) {
                v = *reinterpret_cast<const float4*>(
                        img + (size_t)(iy0 + r) * W_IN + (ix0 + c4));
            } else {
                const int gy = iy0 + r;
                const int gx = ix0 + c4;
                if (gy >= 0 && gy < H_IN && gx >= 0 && gx + 3 < W_IN) {
                    v = *reinterpret_cast<const float4*>(img + (size_t)gy * W_IN + gx);
                } else {
                    v.x = v.y = v.z = v.w = 0.f;
                    if (gy >= 0 && gy < H_IN) {
                        const float* row = img + (size_t)gy * W_IN;
                        if (gx + 0 >= 0 && gx + 0 < W_IN) v.x = row[gx + 0];
                        if (gx + 1 >= 0 && gx + 1 < W_IN) v.y = row[gx + 1];
                        if (gx + 2 >= 0 && gx + 2 < W_IN) v.z = row[gx + 2];
                        if (gx + 3 >= 0 && gx + 3 < W_IN) v.w = row[gx + 3];
                    }
                }
            }
            *reinterpret_cast<float4*>(bufA + r * IN_T + c4) = v;
        }
    }
    __syncthreads();

    // conv1: bufA(s144) -> bufB(142 rows, stride 144). 864 items.
    conv_stage<144, 144, 142, 6, 36, MASK>(bufA, bufB, w1, iy0 + 1, ix0 + 1, H_IN, W_IN);
    __syncthreads();

    // conv2: bufB(s144) -> bufA(140x140, stride 140). 840 items.
    conv_stage<144, 140, 140, 6, 35, MASK>(bufB, bufA, w2, iy0 + 2, ix0 + 2, H_IN, W_IN);
    __syncthreads();

    // pool: bufA(s140) -> bufB(70 rows, stride 72). 630 items.
    pool_stage<140, 72, 70, 18>(bufA, bufB);
    __syncthreads();

    // conv3: bufB(s72) -> bufA(68x68, stride 68). 578 items.
    conv_stage<72, 68, 68, 2, 17, MASK>(bufB, bufA, w3,
                                        by * TILE - 2, bx * TILE - 2, H_PO, W_PO);
    __syncthreads();

    // conv4: bufA(s68) -> bufB(66 rows, stride 68). 561 items.
    conv_stage<68, 68, 66, 2, 17, MASK>(bufA, bufB, w4,
                                        by * TILE - 1, bx * TILE - 1, H_PO, W_PO);
    __syncthreads();

    // conv5: bufB(s68) -> gmem 64x64 (always fully in-image). 1024 items.
    float* optr = out + ((size_t)bz * H_PO + (size_t)by * TILE) * W_PO + bx * TILE;
    conv_stage<68, W_PO, 64, 1, 16, false>(bufB, optr, w5, 0, 0, H_PO, W_PO);
}

__global__ __launch_bounds__(NT, 1)
void fused_net_kernel(const float* __restrict__ x,
                      const float* __restrict__ w1, const float* __restrict__ w2,
                      const float* __restrict__ w3, const float* __restrict__ w4,
                      const float* __restrict__ w5,
                      float* __restrict__ out)
{
    const int bx = blockIdx.x, by = blockIdx.y;
    const bool interior = (bx > 0) & (bx < (W_PO / TILE) - 1) &
                          (by > 0) & (by < (H_PO / TILE) - 1);
    if (interior) run_tile<false>(x, w1, w2, w3, w4, w5, out);
    else          run_tile<true >(x, w1, w2, w3, w4, w5, out);
}

extern "C" void kernel_launch(void* const* d_in, const int* in_sizes, int n_in,
                              void* d_out, int out_size)
{
    const float* x  = (const float*)d_in[0];
    const float* w1 = (const float*)d_in[1];
    const float* w2 = (const float*)d_in[2];
    const float* w3 = (const float*)d_in[3];
    const float* w4 = (const float*)d_in[4];
    const float* w5 = (const float*)d_in[5];
    float* out = (float*)d_out;

    cudaFuncSetAttribute(fused_net_kernel,
                         cudaFuncAttributeMaxDynamicSharedMemorySize, SMEM_BYTES);
    dim3 grid(W_PO / TILE, H_PO / TILE, 4);   // 32 x 32 x 4
    fused_net_kernel<<<grid, NT, SMEM_BYTES>>>(x, w1, w2, w3, w4, w5, out);
}